// round 1
// baseline (speedup 1.0000x reference)
#include <cuda_runtime.h>
#include <math.h>

#define BB 64
#define SS 1024
#define DD 1024
#define EE 8
#define KTOP 2

#define OSPLIT 8                 // o-split for W2 precompute
#define BLOCKS_PER_BATCH 8
#define NBLOCKS_B (BB * BLOCKS_PER_BATCH)          // 512
#define TOK_PER_BLOCK (SS / BLOCKS_PER_BATCH)      // 128
#define WARPS_PER_BLOCK 8
#define TOK_PER_WARP (TOK_PER_BLOCK / WARPS_PER_BLOCK) // 16
#define TGROUP 4

#define MASK_ELEMS (BB * SS * EE)   // 524288
#define IDX_OFF    MASK_ELEMS
#define LOSS_OFF   (MASK_ELEMS + BB * KTOP)

// ---------------- scratch (device globals: no allocation allowed) ----------
__device__ float g_W2part[OSPLIT][EE][DD];   // 256 KB
__device__ float g_W2[EE * DD];              // 32 KB
__device__ float g_b2[EE];
__device__ float g_pScores[NBLOCKS_B][EE];   // per-block partial softmax sums
__device__ float g_pAux[NBLOCKS_B];          // per-block partial aux sums
__device__ float g_mask2d[BB * EE];

// ---------------- Kernel A: partial W2 = key_emb @ Wq (o-split) ------------
// grid (E, OSPLIT), block 256. thread handles 4 contiguous d's (float4).
__global__ void __launch_bounds__(256) wk_a(const float* __restrict__ Wq,
                                            const float* __restrict__ key) {
    int e  = blockIdx.x;
    int oc = blockIdx.y;
    int d  = threadIdx.x * 4;
    const float* wq = Wq + (size_t)(oc * 128) * DD + d;
    const float* ke = key + e * DD + oc * 128;
    float4 acc = make_float4(0.f, 0.f, 0.f, 0.f);
    #pragma unroll 4
    for (int o = 0; o < 128; o++) {
        float k  = __ldg(ke + o);
        float4 w = *(const float4*)(wq + (size_t)o * DD);
        acc.x += k * w.x; acc.y += k * w.y; acc.z += k * w.z; acc.w += k * w.w;
    }
    *(float4*)&g_W2part[oc][e][d] = acc;
}

// ---------------- Kernel A2: reduce o-split partials -> W2 -----------------
__global__ void __launch_bounds__(256) wk_a2() {
    int e = blockIdx.x;
    int d = threadIdx.x * 4;
    float4 s = make_float4(0.f, 0.f, 0.f, 0.f);
    #pragma unroll
    for (int oc = 0; oc < OSPLIT; oc++) {
        float4 p = *(const float4*)&g_W2part[oc][e][d];
        s.x += p.x; s.y += p.y; s.z += p.z; s.w += p.w;
    }
    *(float4*)&g_W2[e * DD + d] = s;
}

// ---------------- Kernel A3: b2 = key_emb @ bq ------------------------------
__global__ void wk_a3(const float* __restrict__ bq, const float* __restrict__ key) {
    int e = threadIdx.x >> 5, lane = threadIdx.x & 31;
    float s = 0.f;
    for (int o = lane; o < DD; o += 32) s += bq[o] * key[e * DD + o];
    #pragma unroll
    for (int off = 16; off > 0; off >>= 1) s += __shfl_xor_sync(0xFFFFFFFFu, s, off);
    if (lane == 0) g_b2[e] = s;
}

// ---------------- Kernel B: main fused pass ---------------------------------
// scores = x . W2^T (+b2) * scale -> softmax(E=8) -> per-batch score sums
// and aux-loss partial sums. 512 blocks (8 per batch), 256 thr, W2 in smem,
// T=4 token register blocking so W2 smem reads amortize 4x.
__global__ void __launch_bounds__(256) wk_b(const float* __restrict__ x) {
    __shared__ float4 s_w2[EE * DD / 4];            // 32 KB
    __shared__ float  s_b2[EE];
    __shared__ float  s_red[WARPS_PER_BLOCK][EE];
    __shared__ float  s_aux[WARPS_PER_BLOCK];

    int tid = threadIdx.x;
    for (int i = tid; i < EE * DD / 4; i += 256)
        s_w2[i] = ((const float4*)g_W2)[i];
    if (tid < EE) s_b2[tid] = g_b2[tid];
    __syncthreads();

    float b2r[EE];
    #pragma unroll
    for (int e = 0; e < EE; e++) b2r[e] = s_b2[e];

    int b    = blockIdx.x / BLOCKS_PER_BATCH;
    int blk  = blockIdx.x % BLOCKS_PER_BATCH;
    int warp = tid >> 5, lane = tid & 31;
    int tokBase = b * SS + blk * TOK_PER_BLOCK + warp * TOK_PER_WARP;

    const float scale = 0.03125f;   // 1024^-0.5 (exact)
    float scoreAcc = 0.f;           // lane e<8 accumulates softmax weight of expert e
    float auxAcc   = 0.f;

    for (int tg = 0; tg < TOK_PER_WARP; tg += TGROUP) {
        float acc[TGROUP][EE];
        #pragma unroll
        for (int t = 0; t < TGROUP; t++)
            #pragma unroll
            for (int e = 0; e < EE; e++) acc[t][e] = 0.f;

        const float* xp0 = x + (size_t)(tokBase + tg) * DD + lane * 4;

        #pragma unroll
        for (int j = 0; j < 8; j++) {
            float4 w[EE];
            #pragma unroll
            for (int e = 0; e < EE; e++)
                w[e] = s_w2[e * 256 + j * 32 + lane];
            #pragma unroll
            for (int t = 0; t < TGROUP; t++) {
                float4 xv = *(const float4*)(xp0 + (size_t)t * DD + j * 128);
                #pragma unroll
                for (int e = 0; e < EE; e++) {
                    acc[t][e] = fmaf(xv.x, w[e].x, acc[t][e]);
                    acc[t][e] = fmaf(xv.y, w[e].y, acc[t][e]);
                    acc[t][e] = fmaf(xv.z, w[e].z, acc[t][e]);
                    acc[t][e] = fmaf(xv.w, w[e].w, acc[t][e]);
                }
            }
        }

        // warp-wide reduce: every lane ends with the full dot for all (t,e)
        #pragma unroll
        for (int t = 0; t < TGROUP; t++)
            #pragma unroll
            for (int e = 0; e < EE; e++) {
                float v = acc[t][e];
                v += __shfl_xor_sync(0xFFFFFFFFu, v, 16);
                v += __shfl_xor_sync(0xFFFFFFFFu, v, 8);
                v += __shfl_xor_sync(0xFFFFFFFFu, v, 4);
                v += __shfl_xor_sync(0xFFFFFFFFu, v, 2);
                v += __shfl_xor_sync(0xFFFFFFFFu, v, 1);
                acc[t][e] = v;
            }

        if (lane < EE) {   // 8 lanes do the softmax (no redundant MUFU)
            #pragma unroll
            for (int t = 0; t < TGROUP; t++) {
                float m = -3.402823466e38f;
                #pragma unroll
                for (int e = 0; e < EE; e++) m = fmaxf(m, acc[t][e] + b2r[e]);
                float se = (acc[t][lane] + b2r[lane] - m) * scale;
                float ex = __expf(se);
                float denom = ex;
                denom += __shfl_xor_sync(0xFFu, denom, 4);
                denom += __shfl_xor_sync(0xFFu, denom, 2);
                denom += __shfl_xor_sync(0xFFu, denom, 1);
                float w = ex / denom;
                scoreAcc += w;
                auxAcc   += w * __logf(w + 1e-9f);
            }
        }
    }

    if (lane < EE) s_red[warp][lane] = scoreAcc;
    float a = auxAcc;   // lanes >=8 hold 0, butterfly is safe
    #pragma unroll
    for (int off = 16; off > 0; off >>= 1) a += __shfl_xor_sync(0xFFFFFFFFu, a, off);
    if (lane == 0) s_aux[warp] = a;
    __syncthreads();

    if (warp == 0) {
        if (lane < EE) {
            float s = 0.f;
            #pragma unroll
            for (int w2 = 0; w2 < WARPS_PER_BLOCK; w2++) s += s_red[w2][lane];
            g_pScores[blockIdx.x][lane] = s;
        }
        if (lane == 0) {
            float s = 0.f;
            #pragma unroll
            for (int w2 = 0; w2 < WARPS_PER_BLOCK; w2++) s += s_aux[w2];
            g_pAux[blockIdx.x] = s;
        }
    }
}

// ---------------- Kernel C: top-k, mask2d, router loss ----------------------
__global__ void wk_c(float* __restrict__ out) {
    __shared__ float s_mask[BB * EE];
    __shared__ float s_auxred[128];
    int tid = threadIdx.x;

    float a = 0.f;
    for (int i = tid; i < NBLOCKS_B; i += 128) a += g_pAux[i];
    s_auxred[tid] = a;

    if (tid < BB) {
        float sc[EE];
        #pragma unroll
        for (int e = 0; e < EE; e++) sc[e] = 0.f;
        for (int p = 0; p < BLOCKS_PER_BATCH; p++)
            #pragma unroll
            for (int e = 0; e < EE; e++)
                sc[e] += g_pScores[tid * BLOCKS_PER_BATCH + p][e];

        // top-2, ties -> lowest index first (jax.lax.top_k stable semantics)
        int i1 = 0; float v1 = sc[0];
        #pragma unroll
        for (int e = 1; e < EE; e++) if (sc[e] > v1) { v1 = sc[e]; i1 = e; }
        int i2 = -1; float v2 = -3.402823466e38f;
        #pragma unroll
        for (int e = 0; e < EE; e++)
            if (e != i1 && sc[e] > v2) { v2 = sc[e]; i2 = e; }

        #pragma unroll
        for (int e = 0; e < EE; e++) {
            float mv = (e == i1 || e == i2) ? 1.0f : 0.0f;
            s_mask[tid * EE + e]   = mv;
            g_mask2d[tid * EE + e] = mv;
        }
        out[IDX_OFF + tid * KTOP + 0] = (float)i1;
        out[IDX_OFF + tid * KTOP + 1] = (float)i2;
    }
    __syncthreads();

    if (tid == 0) {
        float aux = 0.f;
        for (int i = 0; i < 128; i++) aux += s_auxred[i];
        aux /= (float)(BB * SS * EE);

        float cnt[EE];
        #pragma unroll
        for (int e = 0; e < EE; e++) cnt[e] = 0.f;
        for (int b = 0; b < BB; b++)
            #pragma unroll
            for (int e = 0; e < EE; e++) cnt[e] += s_mask[b * EE + e];

        const float ideal = 1.0f / (float)EE;
        const float logideal = logf(ideal);
        float kl = 0.f;
        #pragma unroll
        for (int e = 0; e < EE; e++) {
            float usage = cnt[e] / (float)BB;   // mask2d.sum(0) * S/(B*S)
            kl += ideal * (logideal - logf(usage));
        }
        kl /= (float)EE;
        out[LOSS_OFF] = 1e-3f * kl + 1e-3f * aux;
    }
}

// ---------------- Kernel D: broadcast mask2d -> mask [B,S,E] ----------------
__global__ void __launch_bounds__(256) wk_d(float* __restrict__ out) {
    int i = blockIdx.x * blockDim.x + threadIdx.x;  // float4 index
    int g = i * 4;
    if (g >= MASK_ELEMS) return;
    int b  = g >> 13;        // / (S*E) = /8192
    int e0 = g & 7;          // E=8, 4-aligned
    const float* m = g_mask2d + b * EE + e0;
    float4 v = make_float4(m[0], m[1], m[2], m[3]);
    *(float4*)(out + g) = v;
}

// ---------------- launch ----------------------------------------------------
extern "C" void kernel_launch(void* const* d_in, const int* in_sizes, int n_in,
                              void* d_out, int out_size) {
    const float* x   = (const float*)d_in[0];
    const float* Wq  = (const float*)d_in[1];
    const float* bq  = (const float*)d_in[2];
    const float* key = (const float*)d_in[3];
    float* out = (float*)d_out;

    wk_a<<<dim3(EE, OSPLIT), 256>>>(Wq, key);
    wk_a2<<<EE, 256>>>();
    wk_a3<<<1, 256>>>(bq, key);
    wk_b<<<NBLOCKS_B, 256>>>(x);
    wk_c<<<1, 128>>>(out);
    wk_d<<<(MASK_ELEMS / 4 + 255) / 256, 256>>>(out);
}

// round 3
// speedup vs baseline: 1.2888x; 1.2888x over previous
#include <cuda_runtime.h>
#include <math.h>

#define BB 64
#define SS 1024
#define DD 1024
#define EE 8
#define KTOP 2

#define OSPLIT 32                 // o-split for W2 precompute

// wk_b geometry: 128 tokens per block, 128 threads, token-per-thread
#define BTHREADS 128
#define BLK_TOK 128
#define NBLOCKS_B (BB * SS / BLK_TOK)          // 512
#define BLOCKS_PER_BATCH (SS / BLK_TOK)        // 8
#define DCHUNK 32                              // floats of D per pipeline stage
#define NCHUNK (DD / DCHUNK)                   // 32
#define XROW_F4 9                              // 32 floats + 4 pad = 9 float4 (conflict-free)

#define MASK_ELEMS (BB * SS * EE)   // 524288
#define IDX_OFF    MASK_ELEMS
#define LOSS_OFF   (MASK_ELEMS + BB * KTOP)

// ---------------- scratch (device globals: no allocation allowed) ----------
__device__ float g_W2part[OSPLIT][EE][DD];   // 1 MB
__device__ float g_W2[EE * DD];              // 32 KB
__device__ float g_b2[EE];
__device__ float g_pScores[NBLOCKS_B][EE];   // per-block partial softmax sums
__device__ float g_pAux[NBLOCKS_B];          // per-block partial aux sums
__device__ float g_mask2d[BB * EE];

// ---------------- Kernel A: partial W2 = key_emb @ Wq (o-split) ------------
// grid (E, OSPLIT=32), block 256. thread handles 4 contiguous d's (float4).
__global__ void __launch_bounds__(256) wk_a(const float* __restrict__ Wq,
                                            const float* __restrict__ key) {
    int e  = blockIdx.x;
    int oc = blockIdx.y;
    int d  = threadIdx.x * 4;
    const float* wq = Wq + (size_t)(oc * 32) * DD + d;
    const float* ke = key + e * DD + oc * 32;
    float4 acc = make_float4(0.f, 0.f, 0.f, 0.f);
    #pragma unroll
    for (int o = 0; o < 32; o++) {
        float k  = __ldg(ke + o);
        float4 w = *(const float4*)(wq + (size_t)o * DD);
        acc.x += k * w.x; acc.y += k * w.y; acc.z += k * w.z; acc.w += k * w.w;
    }
    *(float4*)&g_W2part[oc][e][d] = acc;
}

// ---------------- Kernel A2: reduce o-split partials -> W2 -----------------
__global__ void __launch_bounds__(256) wk_a2() {
    int e = blockIdx.x;
    int d = threadIdx.x * 4;
    float4 s = make_float4(0.f, 0.f, 0.f, 0.f);
    #pragma unroll
    for (int oc = 0; oc < OSPLIT; oc++) {
        float4 p = *(const float4*)&g_W2part[oc][e][d];
        s.x += p.x; s.y += p.y; s.z += p.z; s.w += p.w;
    }
    *(float4*)&g_W2[e * DD + d] = s;
}

// ---------------- Kernel A3: b2 = key_emb @ bq ------------------------------
__global__ void wk_a3(const float* __restrict__ bq, const float* __restrict__ key) {
    int e = threadIdx.x >> 5, lane = threadIdx.x & 31;
    float s = 0.f;
    for (int o = lane; o < DD; o += 32) s += bq[o] * key[e * DD + o];
    #pragma unroll
    for (int off = 16; off > 0; off >>= 1) s += __shfl_xor_sync(0xFFFFFFFFu, s, off);
    if (lane == 0) g_b2[e] = s;
}

// ---------------- Kernel B: main fused pass (token-per-thread) --------------
// Each thread owns one token: acc[8] accumulated over D in double-buffered
// smem-staged chunks. Softmax + aux fully per-thread (no cross-lane reduce
// in the hot path). Per-block score/aux reduction at the end.
__global__ void __launch_bounds__(BTHREADS, 8) wk_b(const float* __restrict__ x) {
    __shared__ float4 s_x[2][BLK_TOK * XROW_F4];   // 2 x 18 KB
    __shared__ float4 s_w2[2][EE * (DCHUNK / 4)];  // 2 x 1 KB
    __shared__ float  s_b2[EE];
    __shared__ float  s_red[BTHREADS / 32][EE];
    __shared__ float  s_aux[BTHREADS / 32];

    const int tid  = threadIdx.x;
    const int tok0 = blockIdx.x * BLK_TOK;
    const int r0   = tid >> 3;          // load-phase row within t-group
    const int c0   = tid & 7;           // load-phase col (float4)

    const float4* xg = (const float4*)x;
    const float4* w2g = (const float4*)g_W2;
    const size_t base4 = (size_t)tok0 * (DD / 4);

    if (tid < EE) s_b2[tid] = g_b2[tid];

    float4 rx[8];
    float4 rw;

    // prologue: load chunk 0
    #pragma unroll
    for (int t = 0; t < 8; t++)
        rx[t] = xg[base4 + (size_t)(t * 16 + r0) * (DD / 4) + c0];
    if (tid < 64) rw = w2g[(tid >> 3) * (DD / 4) + (tid & 7)];

    #pragma unroll
    for (int t = 0; t < 8; t++)
        s_x[0][(t * 16 + r0) * XROW_F4 + c0] = rx[t];
    if (tid < 64) s_w2[0][tid] = rw;
    __syncthreads();

    float acc[EE];
    #pragma unroll
    for (int e = 0; e < EE; e++) acc[e] = 0.f;

    for (int c = 0; c < NCHUNK; c++) {
        int buf = c & 1;

        if (c + 1 < NCHUNK) {   // issue next-chunk loads (front-batched)
            #pragma unroll
            for (int t = 0; t < 8; t++)
                rx[t] = xg[base4 + (size_t)(t * 16 + r0) * (DD / 4) + (c + 1) * 8 + c0];
            if (tid < 64) rw = w2g[(tid >> 3) * (DD / 4) + (c + 1) * 8 + (tid & 7)];
        }

        // compute chunk c
        #pragma unroll
        for (int j = 0; j < 8; j++) {
            float4 xv = s_x[buf][tid * XROW_F4 + j];
            #pragma unroll
            for (int e = 0; e < EE; e++) {
                float4 wv = s_w2[buf][e * 8 + j];   // broadcast
                acc[e] = fmaf(xv.x, wv.x, acc[e]);
                acc[e] = fmaf(xv.y, wv.y, acc[e]);
                acc[e] = fmaf(xv.z, wv.z, acc[e]);
                acc[e] = fmaf(xv.w, wv.w, acc[e]);
            }
        }

        if (c + 1 < NCHUNK) {
            __syncthreads();   // all reads of buf^1 (iter c-1) done
            #pragma unroll
            for (int t = 0; t < 8; t++)
                s_x[buf ^ 1][(t * 16 + r0) * XROW_F4 + c0] = rx[t];
            if (tid < 64) s_w2[buf ^ 1][tid] = rw;
            __syncthreads();   // stores visible before next compute
        }
    }

    // ---- per-thread softmax over E=8 (this thread's token) ----
    const float scale = 0.03125f;   // 1024^-0.5
    float z[EE];
    float m = -3.402823466e38f;
    #pragma unroll
    for (int e = 0; e < EE; e++) { z[e] = acc[e] + s_b2[e]; m = fmaxf(m, z[e]); }
    float ex[EE];
    float denom = 0.f;
    #pragma unroll
    for (int e = 0; e < EE; e++) { ex[e] = __expf((z[e] - m) * scale); denom += ex[e]; }
    float rdenom = __frcp_rn(denom);
    float auxAcc = 0.f;
    #pragma unroll
    for (int e = 0; e < EE; e++) {
        float w = ex[e] * rdenom;
        z[e] = w;                               // reuse z[] as weights
        auxAcc += w * __logf(w + 1e-9f);
    }

    // ---- block reduce: per-expert score sums + aux ----
    int warp = tid >> 5, lane = tid & 31;
    #pragma unroll
    for (int e = 0; e < EE; e++) {
        float v = z[e];
        v += __shfl_xor_sync(0xFFFFFFFFu, v, 16);
        v += __shfl_xor_sync(0xFFFFFFFFu, v, 8);
        v += __shfl_xor_sync(0xFFFFFFFFu, v, 4);
        v += __shfl_xor_sync(0xFFFFFFFFu, v, 2);
        v += __shfl_xor_sync(0xFFFFFFFFu, v, 1);
        if (lane == 0) s_red[warp][e] = v;
    }
    float a = auxAcc;
    #pragma unroll
    for (int off = 16; off > 0; off >>= 1) a += __shfl_xor_sync(0xFFFFFFFFu, a, off);
    if (lane == 0) s_aux[warp] = a;
    __syncthreads();

    if (warp == 0) {
        if (lane < EE) {
            float s = 0.f;
            #pragma unroll
            for (int w2 = 0; w2 < BTHREADS / 32; w2++) s += s_red[w2][lane];
            g_pScores[blockIdx.x][lane] = s;
        }
        if (lane == 0) {
            float s = 0.f;
            #pragma unroll
            for (int w2 = 0; w2 < BTHREADS / 32; w2++) s += s_aux[w2];
            g_pAux[blockIdx.x] = s;
        }
    }
}

// ---------------- Kernel C: top-k, mask2d, router loss ----------------------
__global__ void wk_c(float* __restrict__ out) {
    __shared__ float s_mask[BB * EE];
    __shared__ float s_auxred[128];
    int tid = threadIdx.x;

    float a = 0.f;
    for (int i = tid; i < NBLOCKS_B; i += 128) a += g_pAux[i];
    s_auxred[tid] = a;

    if (tid < BB) {
        float sc[EE];
        #pragma unroll
        for (int e = 0; e < EE; e++) sc[e] = 0.f;
        for (int p = 0; p < BLOCKS_PER_BATCH; p++)
            #pragma unroll
            for (int e = 0; e < EE; e++)
                sc[e] += g_pScores[tid * BLOCKS_PER_BATCH + p][e];

        // top-2, ties -> lowest index first (jax.lax.top_k stable semantics)
        int i1 = 0; float v1 = sc[0];
        #pragma unroll
        for (int e = 1; e < EE; e++) if (sc[e] > v1) { v1 = sc[e]; i1 = e; }
        int i2 = -1; float v2 = -3.402823466e38f;
        #pragma unroll
        for (int e = 0; e < EE; e++)
            if (e != i1 && sc[e] > v2) { v2 = sc[e]; i2 = e; }

        #pragma unroll
        for (int e = 0; e < EE; e++) {
            float mv = (e == i1 || e == i2) ? 1.0f : 0.0f;
            s_mask[tid * EE + e]   = mv;
            g_mask2d[tid * EE + e] = mv;
        }
        out[IDX_OFF + tid * KTOP + 0] = (float)i1;
        out[IDX_OFF + tid * KTOP + 1] = (float)i2;
    }
    __syncthreads();

    if (tid == 0) {
        float aux = 0.f;
        for (int i = 0; i < 128; i++) aux += s_auxred[i];
        aux /= (float)(BB * SS * EE);

        float cnt[EE];
        #pragma unroll
        for (int e = 0; e < EE; e++) cnt[e] = 0.f;
        for (int b = 0; b < BB; b++)
            #pragma unroll
            for (int e = 0; e < EE; e++) cnt[e] += s_mask[b * EE + e];

        const float ideal = 1.0f / (float)EE;
        const float logideal = logf(ideal);
        float kl = 0.f;
        #pragma unroll
        for (int e = 0; e < EE; e++) {
            float usage = cnt[e] / (float)BB;
            kl += ideal * (logideal - logf(usage));
        }
        kl /= (float)EE;
        out[LOSS_OFF] = 1e-3f * kl + 1e-3f * aux;
    }
}

// ---------------- Kernel D: broadcast mask2d -> mask [B,S,E] ----------------
__global__ void __launch_bounds__(256) wk_d(float* __restrict__ out) {
    int i = blockIdx.x * blockDim.x + threadIdx.x;  // float4 index
    int g = i * 4;
    if (g >= MASK_ELEMS) return;
    int b  = g >> 13;        // / (S*E) = /8192
    int e0 = g & 7;          // E=8, 4-aligned
    const float* m = g_mask2d + b * EE + e0;
    float4 v = make_float4(m[0], m[1], m[2], m[3]);
    *(float4*)(out + g) = v;
}

// ---------------- launch ----------------------------------------------------
extern "C" void kernel_launch(void* const* d_in, const int* in_sizes, int n_in,
                              void* d_out, int out_size) {
    const float* x   = (const float*)d_in[0];
    const float* Wq  = (const float*)d_in[1];
    const float* bq  = (const float*)d_in[2];
    const float* key = (const float*)d_in[3];
    float* out = (float*)d_out;

    wk_a<<<dim3(EE, OSPLIT), 256>>>(Wq, key);
    wk_a2<<<EE, 256>>>();
    wk_a3<<<1, 256>>>(bq, key);
    wk_b<<<NBLOCKS_B, BTHREADS>>>(x);
    wk_c<<<1, 128>>>(out);
    wk_d<<<(MASK_ELEMS / 4 + 255) / 256, 256>>>(out);
}

// round 4
// speedup vs baseline: 2.2993x; 1.7841x over previous
#include <cuda_runtime.h>
#include <math.h>

#define BB 64
#define SS 1024
#define DD 1024
#define EE 8
#define KTOP 2

#define OSPLIT 32                 // o-split for W2 precompute

// wk_b geometry: warp = 4 token-octets, 2 tokens/lane, 8 tokens/warp
#define BTHREADS 256
#define WARPS_B (BTHREADS / 32)                // 8
#define TOK_PER_WARP 8
#define BLK_TOK (WARPS_B * TOK_PER_WARP)       // 64
#define NBLOCKS_B (BB * SS / BLK_TOK)          // 1024
#define BLOCKS_PER_BATCH (SS / BLK_TOK)        // 16

#define MASK_ELEMS (BB * SS * EE)   // 524288
#define IDX_OFF    MASK_ELEMS
#define LOSS_OFF   (MASK_ELEMS + BB * KTOP)

// ---------------- scratch (device globals: no allocation allowed) ----------
__device__ float g_W2part[OSPLIT][EE][DD];   // 1 MB
__device__ float g_W2[EE * DD];              // 32 KB
__device__ float g_b2[EE];
__device__ float g_pScores[NBLOCKS_B][EE];   // per-block partial softmax sums
__device__ float g_pAux[NBLOCKS_B];          // per-block partial aux sums
__device__ float g_mask2d[BB * EE];

// ---------------- Kernel A: partial W2 = key_emb @ Wq (o-split) ------------
// grid (E, OSPLIT=32), block 256. thread handles 4 contiguous d's (float4).
__global__ void __launch_bounds__(256) wk_a(const float* __restrict__ Wq,
                                            const float* __restrict__ key) {
    int e  = blockIdx.x;
    int oc = blockIdx.y;
    int d  = threadIdx.x * 4;
    const float* wq = Wq + (size_t)(oc * 32) * DD + d;
    const float* ke = key + e * DD + oc * 32;
    float4 acc = make_float4(0.f, 0.f, 0.f, 0.f);
    #pragma unroll
    for (int o = 0; o < 32; o++) {
        float k  = __ldg(ke + o);
        float4 w = *(const float4*)(wq + (size_t)o * DD);
        acc.x += k * w.x; acc.y += k * w.y; acc.z += k * w.z; acc.w += k * w.w;
    }
    *(float4*)&g_W2part[oc][e][d] = acc;
}

// ------------- Kernel A2: reduce o-split partials -> W2, plus b2 -----------
// grid 8 (one block per expert), 256 threads.
__global__ void __launch_bounds__(256) wk_a2(const float* __restrict__ bq,
                                             const float* __restrict__ key) {
    __shared__ float s_part[WARPS_B];
    int e = blockIdx.x;
    int tid = threadIdx.x;
    int d = tid * 4;
    float4 s = make_float4(0.f, 0.f, 0.f, 0.f);
    #pragma unroll
    for (int oc = 0; oc < OSPLIT; oc++) {
        float4 p = *(const float4*)&g_W2part[oc][e][d];
        s.x += p.x; s.y += p.y; s.z += p.z; s.w += p.w;
    }
    *(float4*)&g_W2[e * DD + d] = s;

    // b2[e] = bq . key[e]
    float4 bv = *(const float4*)(bq + d);
    float4 kv = *(const float4*)(key + e * DD + d);
    float p = bv.x * kv.x + bv.y * kv.y + bv.z * kv.z + bv.w * kv.w;
    #pragma unroll
    for (int off = 16; off > 0; off >>= 1) p += __shfl_xor_sync(0xFFFFFFFFu, p, off);
    int warp = tid >> 5, lane = tid & 31;
    if (lane == 0) s_part[warp] = p;
    __syncthreads();
    if (tid == 0) {
        float b2 = 0.f;
        #pragma unroll
        for (int w = 0; w < WARPS_B; w++) b2 += s_part[w];
        g_b2[e] = b2;
    }
}

// ---------------- Kernel B: main fused pass ---------------------------------
// No x staging: lane c=lane&7 owns a 128-float D-slice of its token, reads x
// straight from global (coalesced 128B per octet). W2 in smem only, loaded
// once; no syncthreads in the hot loop. Octet shuffle-reduce at the end.
__global__ void __launch_bounds__(BTHREADS, 5) wk_b(const float* __restrict__ x) {
    __shared__ float4 s_w2[EE * 256];            // 32 KB, [e][j]
    __shared__ float  s_b2[EE];
    __shared__ float  s_red[WARPS_B][EE];
    __shared__ float  s_aux[WARPS_B];

    const int tid = threadIdx.x;
    const float4* w2g = (const float4*)g_W2;
    #pragma unroll
    for (int i = 0; i < 8; i++) s_w2[tid + i * 256] = w2g[tid + i * 256];
    if (tid < EE) s_b2[tid] = g_b2[tid];
    __syncthreads();

    const int warp = tid >> 5, lane = tid & 31;
    const int oct  = lane >> 3;     // which token in the octet group
    const int c    = lane & 7;      // d-slice (float4 column within chunk)
    const int tokBase = blockIdx.x * BLK_TOK + warp * TOK_PER_WARP;

    const float4* xg = (const float4*)x;
    const size_t base0 = (size_t)(tokBase + oct)     * 256 + c;   // token A
    const size_t base1 = (size_t)(tokBase + 4 + oct) * 256 + c;   // token B

    float acc[2][EE];
    #pragma unroll
    for (int t = 0; t < 2; t++)
        #pragma unroll
        for (int e = 0; e < EE; e++) acc[t][e] = 0.f;

    #pragma unroll 2
    for (int i = 0; i < 32; i++) {
        float4 xv0 = xg[base0 + i * 8];
        float4 xv1 = xg[base1 + i * 8];
        #pragma unroll
        for (int e = 0; e < EE; e++) {
            float4 wv = s_w2[e * 256 + i * 8 + c];
            acc[0][e] = fmaf(xv0.x, wv.x, acc[0][e]);
            acc[0][e] = fmaf(xv0.y, wv.y, acc[0][e]);
            acc[0][e] = fmaf(xv0.z, wv.z, acc[0][e]);
            acc[0][e] = fmaf(xv0.w, wv.w, acc[0][e]);
            acc[1][e] = fmaf(xv1.x, wv.x, acc[1][e]);
            acc[1][e] = fmaf(xv1.y, wv.y, acc[1][e]);
            acc[1][e] = fmaf(xv1.z, wv.z, acc[1][e]);
            acc[1][e] = fmaf(xv1.w, wv.w, acc[1][e]);
        }
    }

    // octet reduce: all 8 lanes of the octet end with the full dots
    #pragma unroll
    for (int t = 0; t < 2; t++)
        #pragma unroll
        for (int e = 0; e < EE; e++) {
            float v = acc[t][e];
            v += __shfl_xor_sync(0xFFFFFFFFu, v, 4);
            v += __shfl_xor_sync(0xFFFFFFFFu, v, 2);
            v += __shfl_xor_sync(0xFFFFFFFFu, v, 1);
            acc[t][e] = v;
        }

    // per-token softmax over E=8 (redundant across the 8 octet lanes)
    const float scale = 0.03125f;   // 1024^-0.5
    float b2r[EE];
    #pragma unroll
    for (int e = 0; e < EE; e++) b2r[e] = s_b2[e];

    float scoreAcc[EE];
    #pragma unroll
    for (int e = 0; e < EE; e++) scoreAcc[e] = 0.f;
    float auxAcc = 0.f;
    const float contrib = (c == 0) ? 1.0f : 0.0f;   // count each token once

    #pragma unroll
    for (int t = 0; t < 2; t++) {
        float z[EE];
        float m = -3.402823466e38f;
        #pragma unroll
        for (int e = 0; e < EE; e++) { z[e] = acc[t][e] + b2r[e]; m = fmaxf(m, z[e]); }
        float ex[EE];
        float denom = 0.f;
        #pragma unroll
        for (int e = 0; e < EE; e++) { ex[e] = __expf((z[e] - m) * scale); denom += ex[e]; }
        float rdenom = __frcp_rn(denom);
        #pragma unroll
        for (int e = 0; e < EE; e++) {
            float w = ex[e] * rdenom;
            scoreAcc[e] += contrib * w;
            auxAcc      += contrib * w * __logf(w + 1e-9f);
        }
    }

    // block reduce: per-expert score sums + aux
    #pragma unroll
    for (int e = 0; e < EE; e++) {
        float v = scoreAcc[e];
        v += __shfl_xor_sync(0xFFFFFFFFu, v, 16);
        v += __shfl_xor_sync(0xFFFFFFFFu, v, 8);
        v += __shfl_xor_sync(0xFFFFFFFFu, v, 4);
        v += __shfl_xor_sync(0xFFFFFFFFu, v, 2);
        v += __shfl_xor_sync(0xFFFFFFFFu, v, 1);
        if (lane == 0) s_red[warp][e] = v;
    }
    float a = auxAcc;
    #pragma unroll
    for (int off = 16; off > 0; off >>= 1) a += __shfl_xor_sync(0xFFFFFFFFu, a, off);
    if (lane == 0) s_aux[warp] = a;
    __syncthreads();

    if (warp == 0) {
        if (lane < EE) {
            float s = 0.f;
            #pragma unroll
            for (int w2 = 0; w2 < WARPS_B; w2++) s += s_red[w2][lane];
            g_pScores[blockIdx.x][lane] = s;
        }
        if (lane == 0) {
            float s = 0.f;
            #pragma unroll
            for (int w2 = 0; w2 < WARPS_B; w2++) s += s_aux[w2];
            g_pAux[blockIdx.x] = s;
        }
    }
}

// ---------------- Kernel C: top-k, mask2d, router loss ----------------------
__global__ void wk_c(float* __restrict__ out) {
    __shared__ float s_mask[BB * EE];
    __shared__ float s_auxred[128];
    int tid = threadIdx.x;

    float a = 0.f;
    for (int i = tid; i < NBLOCKS_B; i += 128) a += g_pAux[i];
    s_auxred[tid] = a;

    if (tid < BB) {
        float sc[EE];
        #pragma unroll
        for (int e = 0; e < EE; e++) sc[e] = 0.f;
        for (int p = 0; p < BLOCKS_PER_BATCH; p++)
            #pragma unroll
            for (int e = 0; e < EE; e++)
                sc[e] += g_pScores[tid * BLOCKS_PER_BATCH + p][e];

        // top-2, ties -> lowest index first (jax.lax.top_k stable semantics)
        int i1 = 0; float v1 = sc[0];
        #pragma unroll
        for (int e = 1; e < EE; e++) if (sc[e] > v1) { v1 = sc[e]; i1 = e; }
        int i2 = -1; float v2 = -3.402823466e38f;
        #pragma unroll
        for (int e = 0; e < EE; e++)
            if (e != i1 && sc[e] > v2) { v2 = sc[e]; i2 = e; }

        #pragma unroll
        for (int e = 0; e < EE; e++) {
            float mv = (e == i1 || e == i2) ? 1.0f : 0.0f;
            s_mask[tid * EE + e]   = mv;
            g_mask2d[tid * EE + e] = mv;
        }
        out[IDX_OFF + tid * KTOP + 0] = (float)i1;
        out[IDX_OFF + tid * KTOP + 1] = (float)i2;
    }
    __syncthreads();

    if (tid == 0) {
        float aux = 0.f;
        for (int i = 0; i < 128; i++) aux += s_auxred[i];
        aux /= (float)(BB * SS * EE);

        float cnt[EE];
        #pragma unroll
        for (int e = 0; e < EE; e++) cnt[e] = 0.f;
        for (int b = 0; b < BB; b++)
            #pragma unroll
            for (int e = 0; e < EE; e++) cnt[e] += s_mask[b * EE + e];

        const float ideal = 1.0f / (float)EE;
        const float logideal = logf(ideal);
        float kl = 0.f;
        #pragma unroll
        for (int e = 0; e < EE; e++) {
            float usage = cnt[e] / (float)BB;
            kl += ideal * (logideal - logf(usage));
        }
        kl /= (float)EE;
        out[LOSS_OFF] = 1e-3f * kl + 1e-3f * aux;
    }
}

// ---------------- Kernel D: broadcast mask2d -> mask [B,S,E] ----------------
__global__ void __launch_bounds__(256) wk_d(float* __restrict__ out) {
    int i = blockIdx.x * blockDim.x + threadIdx.x;  // float4 index
    int g = i * 4;
    if (g >= MASK_ELEMS) return;
    int b  = g >> 13;        // / (S*E) = /8192
    int e0 = g & 7;          // E=8, 4-aligned
    const float* m = g_mask2d + b * EE + e0;
    float4 v = make_float4(m[0], m[1], m[2], m[3]);
    *(float4*)(out + g) = v;
}

// ---------------- launch ----------------------------------------------------
extern "C" void kernel_launch(void* const* d_in, const int* in_sizes, int n_in,
                              void* d_out, int out_size) {
    const float* x   = (const float*)d_in[0];
    const float* Wq  = (const float*)d_in[1];
    const float* bq  = (const float*)d_in[2];
    const float* key = (const float*)d_in[3];
    float* out = (float*)d_out;

    wk_a<<<dim3(EE, OSPLIT), 256>>>(Wq, key);
    wk_a2<<<EE, 256>>>(bq, key);
    wk_b<<<NBLOCKS_B, BTHREADS>>>(x);
    wk_c<<<1, 128>>>(out);
    wk_d<<<(MASK_ELEMS / 4 + 255) / 256, 256>>>(out);
}

// round 5
// speedup vs baseline: 2.9753x; 1.2940x over previous
#include <cuda_runtime.h>
#include <math.h>

#define BB 64
#define SS 1024
#define DD 1024
#define EE 8
#define KTOP 2

#define OSPLIT 32                 // o-split for W2 precompute

// wk_b geometry: warp = 4 token-octets, 2 tokens/lane, 8 tokens/warp
#define BTHREADS 256
#define WARPS_B (BTHREADS / 32)                // 8
#define TOK_PER_WARP 8
#define BLK_TOK (WARPS_B * TOK_PER_WARP)       // 64
#define NBLOCKS_B (BB * SS / BLK_TOK)          // 1024
#define BLOCKS_PER_BATCH (SS / BLK_TOK)        // 16

#define MASK_ELEMS (BB * SS * EE)   // 524288
#define IDX_OFF    MASK_ELEMS
#define LOSS_OFF   (MASK_ELEMS + BB * KTOP)

// ---------------- scratch (device globals: no allocation allowed) ----------
__device__ float g_W2part[OSPLIT][EE][DD];   // 1 MB
__device__ float g_W2[EE * DD];              // 32 KB
__device__ float g_b2[EE];
__device__ float g_pScores[NBLOCKS_B][EE];   // per-block partial softmax sums
__device__ float g_pAux[NBLOCKS_B];          // per-block partial aux sums
__device__ float g_mask2d[BB * EE];

// ---------------- Kernel A: partial W2 = key_emb @ Wq (o-split) ------------
__global__ void __launch_bounds__(256) wk_a(const float* __restrict__ Wq,
                                            const float* __restrict__ key) {
    int e  = blockIdx.x;
    int oc = blockIdx.y;
    int d  = threadIdx.x * 4;
    const float* wq = Wq + (size_t)(oc * 32) * DD + d;
    const float* ke = key + e * DD + oc * 32;
    float4 acc = make_float4(0.f, 0.f, 0.f, 0.f);
    #pragma unroll
    for (int o = 0; o < 32; o++) {
        float k  = __ldg(ke + o);
        float4 w = *(const float4*)(wq + (size_t)o * DD);
        acc.x += k * w.x; acc.y += k * w.y; acc.z += k * w.z; acc.w += k * w.w;
    }
    *(float4*)&g_W2part[oc][e][d] = acc;
}

// ------------- Kernel A2: reduce o-split partials -> W2, plus b2 -----------
__global__ void __launch_bounds__(256) wk_a2(const float* __restrict__ bq,
                                             const float* __restrict__ key) {
    __shared__ float s_part[WARPS_B];
    int e = blockIdx.x;
    int tid = threadIdx.x;
    int d = tid * 4;
    float4 s = make_float4(0.f, 0.f, 0.f, 0.f);
    #pragma unroll
    for (int oc = 0; oc < OSPLIT; oc++) {
        float4 p = *(const float4*)&g_W2part[oc][e][d];
        s.x += p.x; s.y += p.y; s.z += p.z; s.w += p.w;
    }
    *(float4*)&g_W2[e * DD + d] = s;

    float4 bv = *(const float4*)(bq + d);
    float4 kv = *(const float4*)(key + e * DD + d);
    float p = bv.x * kv.x + bv.y * kv.y + bv.z * kv.z + bv.w * kv.w;
    #pragma unroll
    for (int off = 16; off > 0; off >>= 1) p += __shfl_xor_sync(0xFFFFFFFFu, p, off);
    int warp = tid >> 5, lane = tid & 31;
    if (lane == 0) s_part[warp] = p;
    __syncthreads();
    if (tid == 0) {
        float b2 = 0.f;
        #pragma unroll
        for (int w = 0; w < WARPS_B; w++) b2 += s_part[w];
        g_b2[e] = b2;
    }
}

// ---------------- Kernel B: main fused pass ---------------------------------
__global__ void __launch_bounds__(BTHREADS, 4) wk_b(const float* __restrict__ x) {
    __shared__ float4 s_w2[EE * 256];            // 32 KB, [e][j]
    __shared__ float  s_b2[EE];
    __shared__ float  s_red[WARPS_B][EE];
    __shared__ float  s_aux[WARPS_B];

    const int tid = threadIdx.x;
    const float4* w2g = (const float4*)g_W2;
    #pragma unroll
    for (int i = 0; i < 8; i++) s_w2[tid + i * 256] = w2g[tid + i * 256];
    if (tid < EE) s_b2[tid] = g_b2[tid];
    __syncthreads();

    const int warp = tid >> 5, lane = tid & 31;
    const int oct  = lane >> 3;     // which token in the octet group
    const int c    = lane & 7;      // d-slice (float4 column within chunk)
    const int tokBase = blockIdx.x * BLK_TOK + warp * TOK_PER_WARP;

    const float4* xg = (const float4*)x;
    const size_t base0 = (size_t)(tokBase + oct)     * 256 + c;   // token A
    const size_t base1 = (size_t)(tokBase + 4 + oct) * 256 + c;   // token B

    float acc[2][EE];
    #pragma unroll
    for (int t = 0; t < 2; t++)
        #pragma unroll
        for (int e = 0; e < EE; e++) acc[t][e] = 0.f;

    #pragma unroll 4
    for (int i = 0; i < 32; i++) {
        float4 xv0 = xg[base0 + i * 8];
        float4 xv1 = xg[base1 + i * 8];
        #pragma unroll
        for (int e = 0; e < EE; e++) {
            float4 wv = s_w2[e * 256 + i * 8 + c];
            acc[0][e] = fmaf(xv0.x, wv.x, acc[0][e]);
            acc[0][e] = fmaf(xv0.y, wv.y, acc[0][e]);
            acc[0][e] = fmaf(xv0.z, wv.z, acc[0][e]);
            acc[0][e] = fmaf(xv0.w, wv.w, acc[0][e]);
            acc[1][e] = fmaf(xv1.x, wv.x, acc[1][e]);
            acc[1][e] = fmaf(xv1.y, wv.y, acc[1][e]);
            acc[1][e] = fmaf(xv1.z, wv.z, acc[1][e]);
            acc[1][e] = fmaf(xv1.w, wv.w, acc[1][e]);
        }
    }

    // octet reduce: all 8 lanes of the octet end with the full dots
    #pragma unroll
    for (int t = 0; t < 2; t++)
        #pragma unroll
        for (int e = 0; e < EE; e++) {
            float v = acc[t][e];
            v += __shfl_xor_sync(0xFFFFFFFFu, v, 4);
            v += __shfl_xor_sync(0xFFFFFFFFu, v, 2);
            v += __shfl_xor_sync(0xFFFFFFFFu, v, 1);
            acc[t][e] = v;
        }

    // per-token softmax over E=8 (redundant across the 8 octet lanes)
    const float scale = 0.03125f;   // 1024^-0.5
    float b2r[EE];
    #pragma unroll
    for (int e = 0; e < EE; e++) b2r[e] = s_b2[e];

    float scoreAcc[EE];
    #pragma unroll
    for (int e = 0; e < EE; e++) scoreAcc[e] = 0.f;
    float auxAcc = 0.f;
    const float contrib = (c == 0) ? 1.0f : 0.0f;   // count each token once

    #pragma unroll
    for (int t = 0; t < 2; t++) {
        float z[EE];
        float m = -3.402823466e38f;
        #pragma unroll
        for (int e = 0; e < EE; e++) { z[e] = acc[t][e] + b2r[e]; m = fmaxf(m, z[e]); }
        float ex[EE];
        float denom = 0.f;
        #pragma unroll
        for (int e = 0; e < EE; e++) { ex[e] = __expf((z[e] - m) * scale); denom += ex[e]; }
        float rdenom = __frcp_rn(denom);
        #pragma unroll
        for (int e = 0; e < EE; e++) {
            float w = ex[e] * rdenom;
            scoreAcc[e] += contrib * w;
            auxAcc      += contrib * w * __logf(w + 1e-9f);
        }
    }

    // block reduce: per-expert score sums + aux
    #pragma unroll
    for (int e = 0; e < EE; e++) {
        float v = scoreAcc[e];
        v += __shfl_xor_sync(0xFFFFFFFFu, v, 16);
        v += __shfl_xor_sync(0xFFFFFFFFu, v, 8);
        v += __shfl_xor_sync(0xFFFFFFFFu, v, 4);
        v += __shfl_xor_sync(0xFFFFFFFFu, v, 2);
        v += __shfl_xor_sync(0xFFFFFFFFu, v, 1);
        if (lane == 0) s_red[warp][e] = v;
    }
    float a = auxAcc;
    #pragma unroll
    for (int off = 16; off > 0; off >>= 1) a += __shfl_xor_sync(0xFFFFFFFFu, a, off);
    if (lane == 0) s_aux[warp] = a;
    __syncthreads();

    if (warp == 0) {
        if (lane < EE) {
            float s = 0.f;
            #pragma unroll
            for (int w2 = 0; w2 < WARPS_B; w2++) s += s_red[w2][lane];
            g_pScores[blockIdx.x][lane] = s;
        }
        if (lane == 0) {
            float s = 0.f;
            #pragma unroll
            for (int w2 = 0; w2 < WARPS_B; w2++) s += s_aux[w2];
            g_pAux[blockIdx.x] = s;
        }
    }
}

// ---------------- Kernel C: top-k, mask2d, router loss (parallel) ----------
// 1024 threads. Half-warp per batch reduces its 16 score partials via float4
// loads + butterfly; aux via tree; final KL across 8 lanes of warp 0.
__global__ void __launch_bounds__(1024) wk_c(float* __restrict__ out) {
    __shared__ float s_mask[BB * EE];
    __shared__ float s_auxw[32];
    int tid  = threadIdx.x;
    int warp = tid >> 5, lane = tid & 31;

    // ---- aux partial: one element per thread (NBLOCKS_B == 1024) ----
    float a = g_pAux[tid];
    #pragma unroll
    for (int off = 16; off > 0; off >>= 1) a += __shfl_xor_sync(0xFFFFFFFFu, a, off);
    if (lane == 0) s_auxw[warp] = a;

    // ---- scores: half-warp per batch (64 batches, 32 warps) ----
    int b   = tid >> 4;            // 0..63
    int sub = tid & 15;            // which partial block of this batch
    const float4* ps = (const float4*)g_pScores;   // [1024][2] float4
    float4 lo = ps[(b * BLOCKS_PER_BATCH + sub) * 2 + 0];
    float4 hi = ps[(b * BLOCKS_PER_BATCH + sub) * 2 + 1];
    #pragma unroll
    for (int off = 8; off > 0; off >>= 1) {
        lo.x += __shfl_xor_sync(0xFFFFFFFFu, lo.x, off);
        lo.y += __shfl_xor_sync(0xFFFFFFFFu, lo.y, off);
        lo.z += __shfl_xor_sync(0xFFFFFFFFu, lo.z, off);
        lo.w += __shfl_xor_sync(0xFFFFFFFFu, lo.w, off);
        hi.x += __shfl_xor_sync(0xFFFFFFFFu, hi.x, off);
        hi.y += __shfl_xor_sync(0xFFFFFFFFu, hi.y, off);
        hi.z += __shfl_xor_sync(0xFFFFFFFFu, hi.z, off);
        hi.w += __shfl_xor_sync(0xFFFFFFFFu, hi.w, off);
    }

    if (sub == 0) {
        float sc[EE] = {lo.x, lo.y, lo.z, lo.w, hi.x, hi.y, hi.z, hi.w};
        // top-2, ties -> lowest index first
        int i1 = 0; float v1 = sc[0];
        #pragma unroll
        for (int e = 1; e < EE; e++) if (sc[e] > v1) { v1 = sc[e]; i1 = e; }
        int i2 = -1; float v2 = -3.402823466e38f;
        #pragma unroll
        for (int e = 0; e < EE; e++)
            if (e != i1 && sc[e] > v2) { v2 = sc[e]; i2 = e; }
        #pragma unroll
        for (int e = 0; e < EE; e++) {
            float mv = (e == i1 || e == i2) ? 1.0f : 0.0f;
            s_mask[b * EE + e]   = mv;
            g_mask2d[b * EE + e] = mv;
        }
        out[IDX_OFF + b * KTOP + 0] = (float)i1;
        out[IDX_OFF + b * KTOP + 1] = (float)i2;
    }
    __syncthreads();

    if (warp == 0) {
        // aux total over 32 warp partials
        float av = s_auxw[lane];
        #pragma unroll
        for (int off = 16; off > 0; off >>= 1) av += __shfl_xor_sync(0xFFFFFFFFu, av, off);
        float aux = av / (float)(BB * SS * EE);

        // per-expert usage counts: lane e<8 sums its column
        float t = 0.f;
        if (lane < EE) {
            float cnt = 0.f;
            #pragma unroll 8
            for (int bb = 0; bb < BB; bb++) cnt += s_mask[bb * EE + lane];
            const float ideal = 1.0f / (float)EE;
            t = ideal * (__logf(ideal) - __logf(cnt / (float)BB));
        }
        #pragma unroll
        for (int off = 4; off > 0; off >>= 1) t += __shfl_xor_sync(0xFFFFFFFFu, t, off);
        if (lane == 0)
            out[LOSS_OFF] = 1e-3f * (t / (float)EE) + 1e-3f * aux;
    }
}

// ---------------- Kernel D: broadcast mask2d -> mask [B,S,E] ----------------
__global__ void __launch_bounds__(256) wk_d(float* __restrict__ out) {
    int i = blockIdx.x * blockDim.x + threadIdx.x;  // float4 index
    int g = i * 4;
    if (g >= MASK_ELEMS) return;
    int b  = g >> 13;        // / (S*E) = /8192
    int e0 = g & 7;          // E=8, 4-aligned
    const float* m = g_mask2d + b * EE + e0;
    float4 v = make_float4(m[0], m[1], m[2], m[3]);
    *(float4*)(out + g) = v;
}

// ---------------- launch ----------------------------------------------------
extern "C" void kernel_launch(void* const* d_in, const int* in_sizes, int n_in,
                              void* d_out, int out_size) {
    const float* x   = (const float*)d_in[0];
    const float* Wq  = (const float*)d_in[1];
    const float* bq  = (const float*)d_in[2];
    const float* key = (const float*)d_in[3];
    float* out = (float*)d_out;

    wk_a<<<dim3(EE, OSPLIT), 256>>>(Wq, key);
    wk_a2<<<EE, 256>>>(bq, key);
    wk_b<<<NBLOCKS_B, BTHREADS>>>(x);
    wk_c<<<1, 1024>>>(out);
    wk_d<<<(MASK_ELEMS / 4 + 255) / 256, 256>>>(out);
}